// round 15
// baseline (speedup 1.0000x reference)
#include <cuda_runtime.h>
#include <cuda_fp16.h>
#include <cstdint>

#define D 128
#define MAXN 50048
#define MAXE 800000
#define CHUNKS 4

// ---------------- scratch (device globals: no allocation allowed) ----------
__device__ __half g_xwA[(size_t)MAXN * D];  // xw ping
__device__ __half g_xwB[(size_t)MAXN * D];  // xw pong
__device__ __half g_h  [(size_t)MAXN * D];  // layer output (fp16)
__device__ float  g_dinv[MAXN];
__device__ int    g_count[MAXN];
__device__ int    g_off[MAXN + 1];
__device__ int    g_cursor[MAXN];
__device__ uint2  g_csr[MAXE];              // {src, w bits} packed per edge
__device__ int    g_bsum[256];
__device__ uint2  g_wfh[3][4096];           // prebuilt fp16 W fragments

// ---------------- helpers ---------------------------------------------------
__device__ __forceinline__ int probe_is64(const void* ei) {
    const uint4* p = (const uint4*)ei;
    uint4 a = p[0], b = p[1], c = p[2], d4 = p[3];
    unsigned int odd = a.y | a.w | b.y | b.w | c.y | c.w | d4.y | d4.w;
    return odd == 0u;
}
__device__ __forceinline__ int load_idx(const void* ei, long long i, int is64) {
    if (is64) return (int)((const long long*)ei)[i];
    return ((const int*)ei)[i];
}
__device__ __forceinline__ uint32_t pack_f16(float x, float y) {
    __half2 p = __floats2half2_rn(x, y);
    return *(uint32_t*)&p;
}

// ---------------- init: zero counts + build fp16 W fragments ----------------
__global__ void k_init(const float* __restrict__ W1,
                       const float* __restrict__ W2,
                       const float* __restrict__ W3, int n) {
    if (blockIdx.x < 48) {
        int gid = blockIdx.x * 256 + threadIdx.x;
        int m   = gid >> 12;
        int idx = gid & 4095;
        const float* W = (m == 0) ? W1 : (m == 1) ? W2 : W3;
        int ln = idx & 31;
        int nt = (idx >> 5) & 15;
        int ks = idx >> 9;
        int gg = ln >> 2, tt = ln & 3;
        int k0 = ks * 16 + tt * 2;
        int nn = nt * 8 + gg;
        float w00 = W[(size_t)k0 * D + nn];
        float w01 = W[(size_t)(k0 + 1) * D + nn];
        float w10 = W[(size_t)(k0 + 8) * D + nn];
        float w11 = W[(size_t)(k0 + 9) * D + nn];
        uint2 v;
        v.x = pack_f16(w00, w01);
        v.y = pack_f16(w10, w11);
        g_wfh[m][idx] = v;
    } else {
        int i = (blockIdx.x - 48) * 256 + threadIdx.x;
        if (i < n) g_count[i] = 0;
    }
}

__global__ void k_count(const void* __restrict__ ei, int e) {
    int is64 = probe_is64(ei);
    int idx = blockIdx.x * blockDim.x + threadIdx.x;
    if (idx >= e) return;
    int d = load_idx(ei, (long long)e + idx, is64);
    atomicAdd(&g_count[d], 1);
}

__global__ void k_scan_p1(int n) {
    int blk = blockIdx.x, t = threadIdx.x;
    int base = blk * 1024 + t * 4;
    int s = 0;
#pragma unroll
    for (int j = 0; j < 4; j++) {
        int i = base + j;
        if (i < n) s += g_count[i];
    }
    __shared__ int sh[256];
    sh[t] = s;
    __syncthreads();
#pragma unroll
    for (int d = 128; d; d >>= 1) {
        if (t < d) sh[t] += sh[t + d];
        __syncthreads();
    }
    if (t == 0) g_bsum[blk] = sh[0];
}

__global__ void k_scan_p23(int n, int nblocks) {
    int blk = blockIdx.x, t = threadIdx.x;
    __shared__ int sh2[256];
    int v2 = (t < nblocks) ? g_bsum[t] : 0;
    sh2[t] = v2;
    __syncthreads();
    for (int d = 1; d < 256; d <<= 1) {
        int a = (t >= d) ? sh2[t - d] : 0;
        __syncthreads();
        sh2[t] += a;
        __syncthreads();
    }
    int bbase = (blk == 0) ? 0 : sh2[blk - 1];
    if (blk == 0 && t == 255) g_off[n] = sh2[255];
    __syncthreads();

    int base = blk * 1024 + t * 4;
    int c[4];
    int s = 0;
#pragma unroll
    for (int j = 0; j < 4; j++) {
        int i = base + j;
        c[j] = (i < n) ? g_count[i] : 0;
        s += c[j];
    }
    __shared__ int sh[256];
    sh[t] = s;
    __syncthreads();
    for (int d = 1; d < 256; d <<= 1) {
        int a = (t >= d) ? sh[t - d] : 0;
        __syncthreads();
        sh[t] += a;
        __syncthreads();
    }
    int tb = bbase + sh[t] - s;
#pragma unroll
    for (int j = 0; j < 4; j++) {
        int i = base + j;
        if (i < n) {
            g_off[i]    = tb;
            g_cursor[i] = tb;
            g_dinv[i]   = rsqrtf((float)c[j] + 1.0f);
            tb += c[j];
        }
    }
}

__global__ void k_fill(const void* __restrict__ ei, int e) {
    int is64 = probe_is64(ei);
    int idx = blockIdx.x * blockDim.x + threadIdx.x;
    if (idx >= e) return;
    int s = load_idx(ei, idx, is64);
    int d = load_idx(ei, (long long)e + idx, is64);
    int pos = atomicAdd(&g_cursor[d], 1);
    float w = g_dinv[s] * g_dinv[d];
    uint2 p;
    p.x = (unsigned)s;
    p.y = __float_as_uint(w);
    g_csr[pos] = p;
}

// ---------------- MMA helper -----------------------------------------------
__device__ __forceinline__ void mma_f16(float c[4], const uint32_t a[4],
                                        uint32_t b0, uint32_t b1) {
    asm volatile(
        "mma.sync.aligned.m16n8k16.row.col.f32.f16.f16.f32 "
        "{%0,%1,%2,%3}, {%4,%5,%6,%7}, {%8,%9}, {%0,%1,%2,%3};"
        : "+f"(c[0]), "+f"(c[1]), "+f"(c[2]), "+f"(c[3])
        : "r"(a[0]), "r"(a[1]), "r"(a[2]), "r"(a[3]), "r"(b0), "r"(b1));
}

// warp-level aggregate of node d (2x unrolled gather loop)
__device__ __forceinline__ float4 agg_node(const __half* __restrict__ src,
                                           int d, int lane, float4 b4) {
    float di = g_dinv[d];
    float self = di * di;
    uint2 us = *(const uint2*)(src + (size_t)d * D + lane * 4);
    float2 s0 = __half22float2(*(const __half2*)&us.x);
    float2 s1 = __half22float2(*(const __half2*)&us.y);
    float4 acc = make_float4(s0.x * self, s0.y * self, s1.x * self, s1.y * self);

    int j0 = g_off[d], j1 = g_off[d + 1];
    int j = j0;
    for (; j + 1 < j1; j += 2) {
        uint2 cp0 = g_csr[j];
        uint2 cp1 = g_csr[j + 1];
        uint2 u0 = *(const uint2*)(src + (size_t)(int)cp0.x * D + lane * 4);
        uint2 u1 = *(const uint2*)(src + (size_t)(int)cp1.x * D + lane * 4);
        float w0 = __uint_as_float(cp0.y);
        float w1 = __uint_as_float(cp1.y);
        float2 a0 = __half22float2(*(const __half2*)&u0.x);
        float2 a1 = __half22float2(*(const __half2*)&u0.y);
        float2 b0 = __half22float2(*(const __half2*)&u1.x);
        float2 b1 = __half22float2(*(const __half2*)&u1.y);
        acc.x += w0 * a0.x + w1 * b0.x;
        acc.y += w0 * a0.y + w1 * b0.y;
        acc.z += w0 * a1.x + w1 * b1.x;
        acc.w += w0 * a1.y + w1 * b1.y;
    }
    if (j < j1) {
        uint2 cp = g_csr[j];
        uint2 u = *(const uint2*)(src + (size_t)(int)cp.x * D + lane * 4);
        float w = __uint_as_float(cp.y);
        float2 f0 = __half22float2(*(const __half2*)&u.x);
        float2 f1 = __half22float2(*(const __half2*)&u.y);
        acc.x += w * f0.x; acc.y += w * f0.y;
        acc.z += w * f1.x; acc.w += w * f1.y;
    }
    acc.x = fmaxf(acc.x + b4.x, 0.f);
    acc.y = fmaxf(acc.y + b4.y, 0.f);
    acc.z = fmaxf(acc.z + b4.z, 0.f);
    acc.w = fmaxf(acc.w + b4.w, 0.f);
    return acc;
}

// ---------------- GEMM kernels (R8-form, proven) ---------------------------
extern __shared__ uint2 s_wf[];  // 32KB W fragments

__global__ void __launch_bounds__(256, 3)
k_gemm1(const float* __restrict__ x, __half* __restrict__ dst, int n) {
    int tid  = threadIdx.x;
    int warp = tid >> 5;
    int lane = tid & 31;
    int g    = lane >> 2;
    int tig  = lane & 3;

    {
        const uint4* src = (const uint4*)g_wfh[0];
        uint4* dstc = (uint4*)s_wf;
#pragma unroll
        for (int v = 0; v < 8; v++) dstc[v * 256 + tid] = src[v * 256 + tid];
    }

    int rbase = blockIdx.x * 128 + warp * 16;
    int r0 = rbase + g;
    int r1 = r0 + 8;
    int r0c = r0 < n ? r0 : n - 1;
    int r1c = r1 < n ? r1 : n - 1;
    const float* p0 = x + (size_t)r0c * D;
    const float* p1 = x + (size_t)r1c * D;

    uint32_t a[8][4];
#pragma unroll
    for (int ks = 0; ks < 8; ks++) {
        int k0 = ks * 16 + tig * 2;
        float2 x0 = *(const float2*)(p0 + k0);
        float2 x1 = *(const float2*)(p1 + k0);
        float2 x2 = *(const float2*)(p0 + k0 + 8);
        float2 x3 = *(const float2*)(p1 + k0 + 8);
        a[ks][0] = pack_f16(x0.x, x0.y);
        a[ks][1] = pack_f16(x1.x, x1.y);
        a[ks][2] = pack_f16(x2.x, x2.y);
        a[ks][3] = pack_f16(x3.x, x3.y);
    }
    __syncthreads();

#pragma unroll 2
    for (int nt = 0; nt < 16; nt++) {
        float c[4] = {0.f, 0.f, 0.f, 0.f};
#pragma unroll
        for (int ks = 0; ks < 8; ks++) {
            uint2 b = s_wf[(ks * 16 + nt) * 32 + lane];
            mma_f16(c, a[ks], b.x, b.y);
        }
        int col = nt * 8 + tig * 2;
        if (r0 < n)
            *(__half2*)(dst + (size_t)r0 * D + col) = __floats2half2_rn(c[0], c[1]);
        if (r1 < n)
            *(__half2*)(dst + (size_t)r1 * D + col) = __floats2half2_rn(c[2], c[3]);
    }
}

// fp16-source GEMM with chunk offset: rows [(blk0+b)*128, ...)
__global__ void __launch_bounds__(256, 3)
k_gemmH(const __half* __restrict__ src, __half* __restrict__ dst,
        int wsel, int n, int blk0) {
    int tid  = threadIdx.x;
    int warp = tid >> 5;
    int lane = tid & 31;
    int g    = lane >> 2;
    int tig  = lane & 3;

    {
        const uint4* wsrc = (const uint4*)g_wfh[wsel];
        uint4* dstc = (uint4*)s_wf;
#pragma unroll
        for (int v = 0; v < 8; v++) dstc[v * 256 + tid] = wsrc[v * 256 + tid];
    }

    int rbase = (blockIdx.x + blk0) * 128 + warp * 16;
    int r0 = rbase + g;
    int r1 = r0 + 8;
    int r0c = r0 < n ? r0 : n - 1;
    int r1c = r1 < n ? r1 : n - 1;
    const __half* p0 = src + (size_t)r0c * D;
    const __half* p1 = src + (size_t)r1c * D;

    uint32_t a[8][4];
#pragma unroll
    for (int ks = 0; ks < 8; ks++) {
        int k0 = ks * 16 + tig * 2;
        a[ks][0] = *(const uint32_t*)(p0 + k0);
        a[ks][1] = *(const uint32_t*)(p1 + k0);
        a[ks][2] = *(const uint32_t*)(p0 + k0 + 8);
        a[ks][3] = *(const uint32_t*)(p1 + k0 + 8);
    }
    __syncthreads();

#pragma unroll 2
    for (int nt = 0; nt < 16; nt++) {
        float c[4] = {0.f, 0.f, 0.f, 0.f};
#pragma unroll
        for (int ks = 0; ks < 8; ks++) {
            uint2 b = s_wf[(ks * 16 + nt) * 32 + lane];
            mma_f16(c, a[ks], b.x, b.y);
        }
        int col = nt * 8 + tig * 2;
        if (r0 < n)
            *(__half2*)(dst + (size_t)r0 * D + col) = __floats2half2_rn(c[0], c[1]);
        if (r1 < n)
            *(__half2*)(dst + (size_t)r1 * D + col) = __floats2half2_rn(c[2], c[3]);
    }
}

// ---------------- aggregation over node range [n0, n1) ---------------------
__global__ void k_aggregate(const __half* __restrict__ src,
                            const float* __restrict__ bias,
                            int n0, int n1) {
    int d = n0 + ((blockIdx.x * blockDim.x + threadIdx.x) >> 5);
    if (d >= n1) return;
    int lane = threadIdx.x & 31;
    float4 b4 = *(const float4*)(bias + lane * 4);
    float4 acc = agg_node(src, d, lane, b4);
    uint2 r;
    r.x = pack_f16(acc.x, acc.y);
    r.y = pack_f16(acc.z, acc.w);
    *(uint2*)(g_h + (size_t)d * D + lane * 4) = r;
}

// ---------------- final aggregate + fc head --------------------------------
__global__ void k_aggfc(const __half* __restrict__ src,
                        const float* __restrict__ bias, int n,
                        const float* __restrict__ Wfc,
                        const float* __restrict__ bfc,
                        float* __restrict__ out) {
    int d = (blockIdx.x * blockDim.x + threadIdx.x) >> 5;
    if (d >= n) return;
    int lane = threadIdx.x & 31;
    float4 b4 = *(const float4*)(bias + lane * 4);
    float4 acc = agg_node(src, d, lane, b4);
    float4 wf = *(const float4*)(Wfc + lane * 4);
    float s = acc.x * wf.x + acc.y * wf.y + acc.z * wf.z + acc.w * wf.w;
#pragma unroll
    for (int o = 16; o; o >>= 1) s += __shfl_xor_sync(0xFFFFFFFFu, s, o);
    if (lane == 0) out[d] = s + bfc[0];
}

// ---------------- launch (pipelined agg->gemm boundaries) ------------------
extern "C" void kernel_launch(void* const* d_in, const int* in_sizes, int n_in,
                              void* d_out, int out_size) {
    const float* x   = (const float*)d_in[0];
    const void*  ei  = d_in[1];
    const float* W1  = (const float*)d_in[2];
    const float* b1  = (const float*)d_in[3];
    const float* W2  = (const float*)d_in[4];
    const float* b2  = (const float*)d_in[5];
    const float* W3  = (const float*)d_in[6];
    const float* b3  = (const float*)d_in[7];
    const float* Wfc = (const float*)d_in[8];
    const float* bfc = (const float*)d_in[9];
    float* out = (float*)d_out;

    int n = in_sizes[0] / D;   // 50000
    int e = in_sizes[1] / 2;   // 800000

    int nb  = (n + 255) / 256;
    int eb  = (e + 255) / 256;
    int sb  = (n + 1023) / 1024;
    int gemm_grid = (n + 127) / 128;           // 391
    int warp_grid = (n + 7) / 8;

    static cudaStream_t s2 = nullptr;
    static cudaEvent_t ev_fork = nullptr, ev_g1 = nullptr;
    static cudaEvent_t ev_gj[2] = {nullptr, nullptr};
    static cudaEvent_t evA[2][CHUNKS];
    static __half *xwA = nullptr, *xwB = nullptr;
    if (!s2) {
        cudaStreamCreateWithFlags(&s2, cudaStreamNonBlocking);
        cudaEventCreateWithFlags(&ev_fork, cudaEventDisableTiming);
        cudaEventCreateWithFlags(&ev_g1, cudaEventDisableTiming);
        for (int l = 0; l < 2; l++) {
            cudaEventCreateWithFlags(&ev_gj[l], cudaEventDisableTiming);
            for (int c = 0; c < CHUNKS; c++)
                cudaEventCreateWithFlags(&evA[l][c], cudaEventDisableTiming);
        }
        cudaFuncSetAttribute(k_gemm1,
                             cudaFuncAttributeMaxDynamicSharedMemorySize, 32768);
        cudaFuncSetAttribute(k_gemmH,
                             cudaFuncAttributeMaxDynamicSharedMemorySize, 32768);
        cudaGetSymbolAddress((void**)&xwA, g_xwA);
        cudaGetSymbolAddress((void**)&xwB, g_xwB);
    }

    // chunk geometry over the 391 GEMM blocks
    int cblk[CHUNKS], cb0[CHUNKS];
    {
        int per = (gemm_grid + CHUNKS - 1) / CHUNKS;
        int acc = 0;
        for (int c = 0; c < CHUNKS; c++) {
            cb0[c]  = acc;
            cblk[c] = (acc + per <= gemm_grid) ? per : (gemm_grid - acc);
            acc += cblk[c];
        }
    }
    __half* hbuf = nullptr;
    cudaGetSymbolAddress((void**)&hbuf, g_h);

    // setup + GEMM1 forked over the CSR build
    k_init<<<48 + nb, 256>>>(W1, W2, W3, n);               // 0
    cudaEventRecord(ev_fork, 0);
    k_count<<<eb, 256>>>(ei, e);                           // 1
    k_scan_p1<<<sb, 256>>>(n);                             // 2
    cudaStreamWaitEvent(s2, ev_fork, 0);
    k_gemm1<<<gemm_grid, 256, 32768, s2>>>(x, xwA, n);     // 3 (|| CSR build)
    cudaEventRecord(ev_g1, s2);
    k_scan_p23<<<sb, 256>>>(n, sb);                        // 4
    k_fill<<<eb, 256>>>(ei, e);                            // 5
    cudaStreamWaitEvent(0, ev_g1, 0);

    // boundary 1: agg1 chunks (stream0) pipelined into gemm2 chunks (s2)
    for (int c = 0; c < CHUNKS; c++) {
        int r0 = cb0[c] * 128;
        int r1 = r0 + cblk[c] * 128; if (r1 > n) r1 = n;
        int wg = (r1 - r0 + 7) / 8;
        k_aggregate<<<wg, 256>>>(xwA, b1, r0, r1);
        cudaEventRecord(evA[0][c], 0);
        cudaStreamWaitEvent(s2, evA[0][c], 0);
        k_gemmH<<<cblk[c], 256, 32768, s2>>>(hbuf, xwB, 1, n, cb0[c]);
    }
    cudaEventRecord(ev_gj[0], s2);
    cudaStreamWaitEvent(0, ev_gj[0], 0);

    // boundary 2: agg2 chunks pipelined into gemm3 chunks
    for (int c = 0; c < CHUNKS; c++) {
        int r0 = cb0[c] * 128;
        int r1 = r0 + cblk[c] * 128; if (r1 > n) r1 = n;
        int wg = (r1 - r0 + 7) / 8;
        k_aggregate<<<wg, 256>>>(xwB, b2, r0, r1);
        cudaEventRecord(evA[1][c], 0);
        cudaStreamWaitEvent(s2, evA[1][c], 0);
        k_gemmH<<<cblk[c], 256, 32768, s2>>>(hbuf, xwA, 2, n, cb0[c]);
    }
    cudaEventRecord(ev_gj[1], s2);
    cudaStreamWaitEvent(0, ev_gj[1], 0);

    // final aggregate + fc
    k_aggfc<<<warp_grid, 256>>>(xwA, b3, n, Wfc, bfc, out);
}

// round 16
// speedup vs baseline: 1.0613x; 1.0613x over previous
#include <cuda_runtime.h>
#include <cuda_fp16.h>
#include <cstdint>

#define D 128
#define MAXN 50048
#define MAXE 800000
#define CSR_GRID 444   // 148 SMs x 3 blocks: all co-resident (required for gsync)

// ---------------- scratch (device globals: no allocation allowed) ----------
__device__ __half g_xwA[(size_t)MAXN * D];  // xw ping
__device__ __half g_xwB[(size_t)MAXN * D];  // xw pong
__device__ __half g_h  [(size_t)MAXN * D];  // layer output (fp16)
__device__ float  g_dinv[MAXN];
__device__ int    g_count[MAXN];
__device__ int    g_off[MAXN + 1];
__device__ int    g_cursor[MAXN];
__device__ uint2  g_csr[MAXE];              // {src, w bits} packed per edge
__device__ int    g_bsum[256];
__device__ uint2  g_wfh[3][4096];           // prebuilt fp16 W fragments
__device__ unsigned g_bcnt = 0;             // grid barrier arrive counter
__device__ unsigned g_bgen = 0;             // grid barrier generation

// ---------------- helpers ---------------------------------------------------
__device__ __forceinline__ int probe_is64(const void* ei) {
    const uint4* p = (const uint4*)ei;
    uint4 a = p[0], b = p[1], c = p[2], d4 = p[3];
    unsigned int odd = a.y | a.w | b.y | b.w | c.y | c.w | d4.y | d4.w;
    return odd == 0u;
}
__device__ __forceinline__ int load_idx(const void* ei, long long i, int is64) {
    if (is64) return (int)((const long long*)ei)[i];
    return ((const int*)ei)[i];
}
__device__ __forceinline__ uint32_t pack_f16(float x, float y) {
    __half2 p = __floats2half2_rn(x, y);
    return *(uint32_t*)&p;
}

// software grid barrier (sense-reversal; counter self-resets => replay-safe)
__device__ __forceinline__ void gsync(int nb) {
    __syncthreads();
    if (threadIdx.x == 0) {
        __threadfence();
        unsigned gen = atomicAdd(&g_bgen, 0u);     // capture BEFORE arriving
        unsigned old = atomicAdd(&g_bcnt, 1u);
        if (old == (unsigned)nb - 1u) {
            atomicExch(&g_bcnt, 0u);
            __threadfence();
            atomicAdd(&g_bgen, 1u);
        } else {
            while (atomicAdd(&g_bgen, 0u) == gen) {}
        }
        __threadfence();
    }
    __syncthreads();
}

// ---------------- fused CSR build: zero -> count -> scan -> fill -----------
__global__ void __launch_bounds__(256, 3)
k_csr(const void* __restrict__ ei, int e, int n) {
    int tid = threadIdx.x, blk = blockIdx.x;
    int gid = blk * 256 + tid;
    const int gstride = CSR_GRID * 256;
    int is64 = probe_is64(ei);
    __shared__ int sh[256];

    // phase 0: zero counts (one stride step covers n)
    for (int i = gid; i < n; i += gstride) g_count[i] = 0;
    gsync(CSR_GRID);

    // phase 1: count in-degrees
    for (int i = gid; i < e; i += gstride) {
        int d = load_idx(ei, (long long)e + i, is64);
        atomicAdd(&g_count[d], 1);
    }
    gsync(CSR_GRID);

    // phase 2a: per-block tile scan (tile = 256 nodes, 1 node/thread)
    int nsb = (n + 255) >> 8;                  // 196 scan tiles
    int node = blk * 256 + tid;
    int cv = 0;
    if (blk < nsb && node < n) cv = g_count[node];
    sh[tid] = cv;
    __syncthreads();
    for (int dstep = 1; dstep < 256; dstep <<= 1) {
        int add = (tid >= dstep) ? sh[tid - dstep] : 0;
        __syncthreads();
        sh[tid] += add;
        __syncthreads();
    }
    int excl = sh[tid] - cv;                   // exclusive within tile
    if (blk < nsb && tid == 255) g_bsum[blk] = sh[255];
    gsync(CSR_GRID);

    // phase 2b: every block redundantly scans the tile sums
    int v2 = (tid < nsb) ? g_bsum[tid] : 0;
    sh[tid] = v2;
    __syncthreads();
    for (int dstep = 1; dstep < 256; dstep <<= 1) {
        int add = (tid >= dstep) ? sh[tid - dstep] : 0;
        __syncthreads();
        sh[tid] += add;
        __syncthreads();
    }
    if (blk == 0 && tid == nsb - 1) g_off[n] = sh[nsb - 1];
    if (blk < nsb) {
        int bbase = (blk == 0) ? 0 : sh[blk - 1];
        if (node < n) {
            int off = bbase + excl;
            g_off[node]    = off;
            g_cursor[node] = off;
            g_dinv[node]   = rsqrtf((float)cv + 1.0f);
        }
    }
    gsync(CSR_GRID);

    // phase 3: fill CSR (packed {src, weight})
    for (int i = gid; i < e; i += gstride) {
        int s = load_idx(ei, i, is64);
        int d = load_idx(ei, (long long)e + i, is64);
        int pos = atomicAdd(&g_cursor[d], 1);
        float w = g_dinv[s] * g_dinv[d];
        uint2 p;
        p.x = (unsigned)s;
        p.y = __float_as_uint(w);
        g_csr[pos] = p;
    }
}

// ---------------- W fragment build (once) ----------------------------------
__global__ void k_initw(const float* __restrict__ W1,
                        const float* __restrict__ W2,
                        const float* __restrict__ W3) {
    int gid = blockIdx.x * 256 + threadIdx.x;   // 0..12287
    int m   = gid >> 12;
    int idx = gid & 4095;
    const float* W = (m == 0) ? W1 : (m == 1) ? W2 : W3;
    int ln = idx & 31;
    int nt = (idx >> 5) & 15;
    int ks = idx >> 9;
    int gg = ln >> 2, tt = ln & 3;
    int k0 = ks * 16 + tt * 2;
    int nn = nt * 8 + gg;
    float w00 = W[(size_t)k0 * D + nn];
    float w01 = W[(size_t)(k0 + 1) * D + nn];
    float w10 = W[(size_t)(k0 + 8) * D + nn];
    float w11 = W[(size_t)(k0 + 9) * D + nn];
    uint2 v;
    v.x = pack_f16(w00, w01);
    v.y = pack_f16(w10, w11);
    g_wfh[m][idx] = v;
}

// ---------------- MMA helper -----------------------------------------------
__device__ __forceinline__ void mma_f16(float c[4], const uint32_t a[4],
                                        uint32_t b0, uint32_t b1) {
    asm volatile(
        "mma.sync.aligned.m16n8k16.row.col.f32.f16.f16.f32 "
        "{%0,%1,%2,%3}, {%4,%5,%6,%7}, {%8,%9}, {%0,%1,%2,%3};"
        : "+f"(c[0]), "+f"(c[1]), "+f"(c[2]), "+f"(c[3])
        : "r"(a[0]), "r"(a[1]), "r"(a[2]), "r"(a[3]), "r"(b0), "r"(b1));
}

// warp-level aggregate of node d (2x unrolled gather loop)
__device__ __forceinline__ float4 agg_node(const __half* __restrict__ src,
                                           int d, int lane, float4 b4) {
    float di = g_dinv[d];
    float self = di * di;
    uint2 us = *(const uint2*)(src + (size_t)d * D + lane * 4);
    float2 s0 = __half22float2(*(const __half2*)&us.x);
    float2 s1 = __half22float2(*(const __half2*)&us.y);
    float4 acc = make_float4(s0.x * self, s0.y * self, s1.x * self, s1.y * self);

    int j0 = g_off[d], j1 = g_off[d + 1];
    int j = j0;
    for (; j + 1 < j1; j += 2) {
        uint2 cp0 = g_csr[j];
        uint2 cp1 = g_csr[j + 1];
        uint2 u0 = *(const uint2*)(src + (size_t)(int)cp0.x * D + lane * 4);
        uint2 u1 = *(const uint2*)(src + (size_t)(int)cp1.x * D + lane * 4);
        float w0 = __uint_as_float(cp0.y);
        float w1 = __uint_as_float(cp1.y);
        float2 a0 = __half22float2(*(const __half2*)&u0.x);
        float2 a1 = __half22float2(*(const __half2*)&u0.y);
        float2 b0 = __half22float2(*(const __half2*)&u1.x);
        float2 b1 = __half22float2(*(const __half2*)&u1.y);
        acc.x += w0 * a0.x + w1 * b0.x;
        acc.y += w0 * a0.y + w1 * b0.y;
        acc.z += w0 * a1.x + w1 * b1.x;
        acc.w += w0 * a1.y + w1 * b1.y;
    }
    if (j < j1) {
        uint2 cp = g_csr[j];
        uint2 u = *(const uint2*)(src + (size_t)(int)cp.x * D + lane * 4);
        float w = __uint_as_float(cp.y);
        float2 f0 = __half22float2(*(const __half2*)&u.x);
        float2 f1 = __half22float2(*(const __half2*)&u.y);
        acc.x += w * f0.x; acc.y += w * f0.y;
        acc.z += w * f1.x; acc.w += w * f1.y;
    }
    acc.x = fmaxf(acc.x + b4.x, 0.f);
    acc.y = fmaxf(acc.y + b4.y, 0.f);
    acc.z = fmaxf(acc.z + b4.z, 0.f);
    acc.w = fmaxf(acc.w + b4.w, 0.f);
    return acc;
}

// ---------------- GEMM kernels (R8-form, proven) ---------------------------
extern __shared__ uint2 s_wf[];  // 32KB W fragments

__global__ void __launch_bounds__(256, 3)
k_gemm1(const float* __restrict__ x, __half* __restrict__ dst, int n) {
    int tid  = threadIdx.x;
    int warp = tid >> 5;
    int lane = tid & 31;
    int g    = lane >> 2;
    int tig  = lane & 3;

    {
        const uint4* src = (const uint4*)g_wfh[0];
        uint4* dstc = (uint4*)s_wf;
#pragma unroll
        for (int v = 0; v < 8; v++) dstc[v * 256 + tid] = src[v * 256 + tid];
    }

    int rbase = blockIdx.x * 128 + warp * 16;
    int r0 = rbase + g;
    int r1 = r0 + 8;
    int r0c = r0 < n ? r0 : n - 1;
    int r1c = r1 < n ? r1 : n - 1;
    const float* p0 = x + (size_t)r0c * D;
    const float* p1 = x + (size_t)r1c * D;

    uint32_t a[8][4];
#pragma unroll
    for (int ks = 0; ks < 8; ks++) {
        int k0 = ks * 16 + tig * 2;
        float2 x0 = *(const float2*)(p0 + k0);
        float2 x1 = *(const float2*)(p1 + k0);
        float2 x2 = *(const float2*)(p0 + k0 + 8);
        float2 x3 = *(const float2*)(p1 + k0 + 8);
        a[ks][0] = pack_f16(x0.x, x0.y);
        a[ks][1] = pack_f16(x1.x, x1.y);
        a[ks][2] = pack_f16(x2.x, x2.y);
        a[ks][3] = pack_f16(x3.x, x3.y);
    }
    __syncthreads();

#pragma unroll 2
    for (int nt = 0; nt < 16; nt++) {
        float c[4] = {0.f, 0.f, 0.f, 0.f};
#pragma unroll
        for (int ks = 0; ks < 8; ks++) {
            uint2 b = s_wf[(ks * 16 + nt) * 32 + lane];
            mma_f16(c, a[ks], b.x, b.y);
        }
        int col = nt * 8 + tig * 2;
        if (r0 < n)
            *(__half2*)(dst + (size_t)r0 * D + col) = __floats2half2_rn(c[0], c[1]);
        if (r1 < n)
            *(__half2*)(dst + (size_t)r1 * D + col) = __floats2half2_rn(c[2], c[3]);
    }
}

__global__ void __launch_bounds__(256, 3)
k_gemmH(const __half* __restrict__ src, __half* __restrict__ dst,
        int wsel, int n) {
    int tid  = threadIdx.x;
    int warp = tid >> 5;
    int lane = tid & 31;
    int g    = lane >> 2;
    int tig  = lane & 3;

    {
        const uint4* wsrc = (const uint4*)g_wfh[wsel];
        uint4* dstc = (uint4*)s_wf;
#pragma unroll
        for (int v = 0; v < 8; v++) dstc[v * 256 + tid] = wsrc[v * 256 + tid];
    }

    int rbase = blockIdx.x * 128 + warp * 16;
    int r0 = rbase + g;
    int r1 = r0 + 8;
    int r0c = r0 < n ? r0 : n - 1;
    int r1c = r1 < n ? r1 : n - 1;
    const __half* p0 = src + (size_t)r0c * D;
    const __half* p1 = src + (size_t)r1c * D;

    uint32_t a[8][4];
#pragma unroll
    for (int ks = 0; ks < 8; ks++) {
        int k0 = ks * 16 + tig * 2;
        a[ks][0] = *(const uint32_t*)(p0 + k0);
        a[ks][1] = *(const uint32_t*)(p1 + k0);
        a[ks][2] = *(const uint32_t*)(p0 + k0 + 8);
        a[ks][3] = *(const uint32_t*)(p1 + k0 + 8);
    }
    __syncthreads();

#pragma unroll 2
    for (int nt = 0; nt < 16; nt++) {
        float c[4] = {0.f, 0.f, 0.f, 0.f};
#pragma unroll
        for (int ks = 0; ks < 8; ks++) {
            uint2 b = s_wf[(ks * 16 + nt) * 32 + lane];
            mma_f16(c, a[ks], b.x, b.y);
        }
        int col = nt * 8 + tig * 2;
        if (r0 < n)
            *(__half2*)(dst + (size_t)r0 * D + col) = __floats2half2_rn(c[0], c[1]);
        if (r1 < n)
            *(__half2*)(dst + (size_t)r1 * D + col) = __floats2half2_rn(c[2], c[3]);
    }
}

// ---------------- aggregation (full range) ----------------------------------
__global__ void k_aggregate(const __half* __restrict__ src,
                            const float* __restrict__ bias, int n) {
    int d = (blockIdx.x * blockDim.x + threadIdx.x) >> 5;
    if (d >= n) return;
    int lane = threadIdx.x & 31;
    float4 b4 = *(const float4*)(bias + lane * 4);
    float4 acc = agg_node(src, d, lane, b4);
    uint2 r;
    r.x = pack_f16(acc.x, acc.y);
    r.y = pack_f16(acc.z, acc.w);
    *(uint2*)(g_h + (size_t)d * D + lane * 4) = r;
}

// ---------------- final aggregate + fc head ---------------------------------
__global__ void k_aggfc(const __half* __restrict__ src,
                        const float* __restrict__ bias, int n,
                        const float* __restrict__ Wfc,
                        const float* __restrict__ bfc,
                        float* __restrict__ out) {
    int d = (blockIdx.x * blockDim.x + threadIdx.x) >> 5;
    if (d >= n) return;
    int lane = threadIdx.x & 31;
    float4 b4 = *(const float4*)(bias + lane * 4);
    float4 acc = agg_node(src, d, lane, b4);
    float4 wf = *(const float4*)(Wfc + lane * 4);
    float s = acc.x * wf.x + acc.y * wf.y + acc.z * wf.z + acc.w * wf.w;
#pragma unroll
    for (int o = 16; o; o >>= 1) s += __shfl_xor_sync(0xFFFFFFFFu, s, o);
    if (lane == 0) out[d] = s + bfc[0];
}

// ---------------- launch -----------------------------------------------------
extern "C" void kernel_launch(void* const* d_in, const int* in_sizes, int n_in,
                              void* d_out, int out_size) {
    const float* x   = (const float*)d_in[0];
    const void*  ei  = d_in[1];
    const float* W1  = (const float*)d_in[2];
    const float* b1  = (const float*)d_in[3];
    const float* W2  = (const float*)d_in[4];
    const float* b2  = (const float*)d_in[5];
    const float* W3  = (const float*)d_in[6];
    const float* b3  = (const float*)d_in[7];
    const float* Wfc = (const float*)d_in[8];
    const float* bfc = (const float*)d_in[9];
    float* out = (float*)d_out;

    int n = in_sizes[0] / D;   // 50000
    int e = in_sizes[1] / 2;   // 800000

    int gemm_grid = (n + 127) / 128;   // 391
    int warp_grid = (n + 7) / 8;

    static cudaStream_t s2 = nullptr;
    static cudaEvent_t ev_fork = nullptr, ev_g1 = nullptr;
    static __half *xwA = nullptr, *xwB = nullptr, *hbuf = nullptr;
    if (!s2) {
        cudaStreamCreateWithFlags(&s2, cudaStreamNonBlocking);
        cudaEventCreateWithFlags(&ev_fork, cudaEventDisableTiming);
        cudaEventCreateWithFlags(&ev_g1, cudaEventDisableTiming);
        cudaFuncSetAttribute(k_gemm1,
                             cudaFuncAttributeMaxDynamicSharedMemorySize, 32768);
        cudaFuncSetAttribute(k_gemmH,
                             cudaFuncAttributeMaxDynamicSharedMemorySize, 32768);
        cudaGetSymbolAddress((void**)&xwA, g_xwA);
        cudaGetSymbolAddress((void**)&xwB, g_xwB);
        cudaGetSymbolAddress((void**)&hbuf, g_h);
    }

    // fork: CSR build (one persistent kernel) || W-frag build + GEMM1
    cudaEventRecord(ev_fork, 0);
    k_csr<<<CSR_GRID, 256>>>(ei, e, n);                    // 0 (stream 0)
    cudaStreamWaitEvent(s2, ev_fork, 0);
    k_initw<<<48, 256, 0, s2>>>(W1, W2, W3);               // 1 (s2)
    k_gemm1<<<gemm_grid, 256, 32768, s2>>>(x, xwA, n);     // 2 (s2)
    cudaEventRecord(ev_g1, s2);
    cudaStreamWaitEvent(0, ev_g1, 0);                      // join

    // layer chain (proven R13 kernels)
    k_aggregate<<<warp_grid, 256>>>(xwA, b1, n);           // 3 <- ncu target
    k_gemmH<<<gemm_grid, 256, 32768>>>(hbuf, xwB, 1, n);   // 4
    k_aggregate<<<warp_grid, 256>>>(xwB, b2, n);           // 5
    k_gemmH<<<gemm_grid, 256, 32768>>>(hbuf, xwA, 2, n);   // 6
    k_aggfc<<<warp_grid, 256>>>(xwA, b3, n, Wfc, bfc, out);// 7
}

// round 17
// speedup vs baseline: 1.3163x; 1.2403x over previous
#include <cuda_runtime.h>
#include <cuda_fp16.h>
#include <cstdint>

#define D 128
#define MAXN 50048
#define MAXE 800000

// ---------------- scratch (device globals: no allocation allowed) ----------
__device__ __half g_xwh[(size_t)MAXN * D];  // x @ W (fp16)
__device__ __half g_h  [(size_t)MAXN * D];  // layer output (fp16)
__device__ float  g_dinv[MAXN];
__device__ int    g_count[MAXN];
__device__ int    g_off[MAXN + 1];
__device__ int    g_cursor[MAXN];
__device__ uint2  g_csr[MAXE];              // {src, w bits} packed per edge
__device__ int    g_bsum[256];
__device__ uint2  g_wfh[3][4096];           // prebuilt fp16 W fragments

// ---------------- dtype probe ----------------------------------------------
__device__ __forceinline__ int probe_is64(const void* ei) {
    const uint4* p = (const uint4*)ei;
    uint4 a = p[0], b = p[1], c = p[2], d4 = p[3];
    unsigned int odd = a.y | a.w | b.y | b.w | c.y | c.w | d4.y | d4.w;
    return odd == 0u;
}
__device__ __forceinline__ int load_idx(const void* ei, long long i, int is64) {
    if (is64) return (int)((const long long*)ei)[i];
    return ((const int*)ei)[i];
}

__device__ __forceinline__ uint32_t pack_f16(float x, float y) {
    __half2 p = __floats2half2_rn(x, y);
    return *(uint32_t*)&p;
}

// packed f32x2 helpers (FFMA2 path — only reachable via explicit PTX)
__device__ __forceinline__ unsigned long long pk2(float x, float y) {
    unsigned long long r;
    asm("mov.b64 %0, {%1, %2};" : "=l"(r) : "f"(x), "f"(y));
    return r;
}
__device__ __forceinline__ float2 upk2(unsigned long long v) {
    float2 f;
    asm("mov.b64 {%0, %1}, %2;" : "=f"(f.x), "=f"(f.y) : "l"(v));
    return f;
}
__device__ __forceinline__ void fma2(unsigned long long& acc,
                                     unsigned long long a,
                                     unsigned long long b) {
    asm("fma.rn.f32x2 %0, %1, %2, %0;" : "+l"(acc) : "l"(a), "l"(b));
}

// ---------------- init: zero counts + build fp16 W fragments ---------------
__global__ void k_init(const float* __restrict__ W1,
                       const float* __restrict__ W2,
                       const float* __restrict__ W3, int n) {
    if (blockIdx.x < 48) {
        int gid = blockIdx.x * 256 + threadIdx.x;     // 0..12287
        int m   = gid >> 12;                          // matrix 0..2
        int idx = gid & 4095;
        const float* W = (m == 0) ? W1 : (m == 1) ? W2 : W3;
        int ln = idx & 31;
        int nt = (idx >> 5) & 15;
        int ks = idx >> 9;
        int gg = ln >> 2, tt = ln & 3;
        int k0 = ks * 16 + tt * 2;
        int nn = nt * 8 + gg;
        float w00 = W[(size_t)k0 * D + nn];
        float w01 = W[(size_t)(k0 + 1) * D + nn];
        float w10 = W[(size_t)(k0 + 8) * D + nn];
        float w11 = W[(size_t)(k0 + 9) * D + nn];
        uint2 v;
        v.x = pack_f16(w00, w01);
        v.y = pack_f16(w10, w11);
        g_wfh[m][idx] = v;
    } else {
        int i = (blockIdx.x - 48) * 256 + threadIdx.x;
        if (i < n) g_count[i] = 0;
    }
}

__global__ void k_count(const void* __restrict__ ei, int e) {
    int is64 = probe_is64(ei);
    int idx = blockIdx.x * blockDim.x + threadIdx.x;
    if (idx >= e) return;
    int d = load_idx(ei, (long long)e + idx, is64);
    atomicAdd(&g_count[d], 1);
}

__global__ void k_scan_p1(int n) {
    int blk = blockIdx.x, t = threadIdx.x;
    int base = blk * 1024 + t * 4;
    int s = 0;
#pragma unroll
    for (int j = 0; j < 4; j++) {
        int i = base + j;
        if (i < n) s += g_count[i];
    }
    __shared__ int sh[256];
    sh[t] = s;
    __syncthreads();
#pragma unroll
    for (int d = 128; d; d >>= 1) {
        if (t < d) sh[t] += sh[t + d];
        __syncthreads();
    }
    if (t == 0) g_bsum[blk] = sh[0];
}

__global__ void k_scan_p23(int n, int nblocks) {
    int blk = blockIdx.x, t = threadIdx.x;
    __shared__ int sh2[256];
    int v2 = (t < nblocks) ? g_bsum[t] : 0;
    sh2[t] = v2;
    __syncthreads();
    for (int d = 1; d < 256; d <<= 1) {
        int a = (t >= d) ? sh2[t - d] : 0;
        __syncthreads();
        sh2[t] += a;
        __syncthreads();
    }
    int bbase = (blk == 0) ? 0 : sh2[blk - 1];
    if (blk == 0 && t == 255) g_off[n] = sh2[255];
    __syncthreads();

    int base = blk * 1024 + t * 4;
    int c[4];
    int s = 0;
#pragma unroll
    for (int j = 0; j < 4; j++) {
        int i = base + j;
        c[j] = (i < n) ? g_count[i] : 0;
        s += c[j];
    }
    __shared__ int sh[256];
    sh[t] = s;
    __syncthreads();
    for (int d = 1; d < 256; d <<= 1) {
        int a = (t >= d) ? sh[t - d] : 0;
        __syncthreads();
        sh[t] += a;
        __syncthreads();
    }
    int tb = bbase + sh[t] - s;
#pragma unroll
    for (int j = 0; j < 4; j++) {
        int i = base + j;
        if (i < n) {
            g_off[i]    = tb;
            g_cursor[i] = tb;
            g_dinv[i]   = rsqrtf((float)c[j] + 1.0f);
            tb += c[j];
        }
    }
}

__global__ void k_fill(const void* __restrict__ ei, int e) {
    int is64 = probe_is64(ei);
    int idx = blockIdx.x * blockDim.x + threadIdx.x;
    if (idx >= e) return;
    int s = load_idx(ei, idx, is64);
    int d = load_idx(ei, (long long)e + idx, is64);
    int pos = atomicAdd(&g_cursor[d], 1);
    float w = g_dinv[s] * g_dinv[d];
    uint2 p;
    p.x = (unsigned)s;
    p.y = __float_as_uint(w);
    g_csr[pos] = p;
}

// ---------------- tensor-core GEMM (R8 form: direct epilogue) --------------
__device__ __forceinline__ void mma_f16(float c[4], const uint32_t a[4],
                                        uint32_t b0, uint32_t b1) {
    asm volatile(
        "mma.sync.aligned.m16n8k16.row.col.f32.f16.f16.f32 "
        "{%0,%1,%2,%3}, {%4,%5,%6,%7}, {%8,%9}, {%0,%1,%2,%3};"
        : "+f"(c[0]), "+f"(c[1]), "+f"(c[2]), "+f"(c[3])
        : "r"(a[0]), "r"(a[1]), "r"(a[2]), "r"(a[3]), "r"(b0), "r"(b1));
}

extern __shared__ uint2 s_wf[];  // [8 ksteps][16 ntiles][32 lanes] = 32KB

__global__ void __launch_bounds__(256, 3)
k_gemm_mma(const float* __restrict__ Ain, int wsel, int n, int useH) {
    int tid  = threadIdx.x;
    int warp = tid >> 5;
    int lane = tid & 31;
    int g    = lane >> 2;
    int tig  = lane & 3;

    // coalesced copy of prebuilt fragments: 8 x uint4 per thread (32KB)
    {
        const uint4* src = (const uint4*)g_wfh[wsel];
        uint4* dst = (uint4*)s_wf;
#pragma unroll
        for (int v = 0; v < 8; v++) dst[v * 256 + tid] = src[v * 256 + tid];
    }

    int rbase = blockIdx.x * 128 + warp * 16;
    int r0 = rbase + g;
    int r1 = r0 + 8;
    int r0c = r0 < n ? r0 : n - 1;
    int r1c = r1 < n ? r1 : n - 1;

    uint32_t a[8][4];
    if (useH) {
        const __half* p0 = g_h + (size_t)r0c * D;
        const __half* p1 = g_h + (size_t)r1c * D;
#pragma unroll
        for (int ks = 0; ks < 8; ks++) {
            int k0 = ks * 16 + tig * 2;
            a[ks][0] = *(const uint32_t*)(p0 + k0);
            a[ks][1] = *(const uint32_t*)(p1 + k0);
            a[ks][2] = *(const uint32_t*)(p0 + k0 + 8);
            a[ks][3] = *(const uint32_t*)(p1 + k0 + 8);
        }
    } else {
        const float* p0 = Ain + (size_t)r0c * D;
        const float* p1 = Ain + (size_t)r1c * D;
#pragma unroll
        for (int ks = 0; ks < 8; ks++) {
            int k0 = ks * 16 + tig * 2;
            float2 x0 = *(const float2*)(p0 + k0);
            float2 x1 = *(const float2*)(p1 + k0);
            float2 x2 = *(const float2*)(p0 + k0 + 8);
            float2 x3 = *(const float2*)(p1 + k0 + 8);
            a[ks][0] = pack_f16(x0.x, x0.y);
            a[ks][1] = pack_f16(x1.x, x1.y);
            a[ks][2] = pack_f16(x2.x, x2.y);
            a[ks][3] = pack_f16(x3.x, x3.y);
        }
    }
    __syncthreads();

#pragma unroll 2
    for (int nt = 0; nt < 16; nt++) {
        float c[4] = {0.f, 0.f, 0.f, 0.f};
#pragma unroll
        for (int ks = 0; ks < 8; ks++) {
            uint2 b = s_wf[(ks * 16 + nt) * 32 + lane];
            mma_f16(c, a[ks], b.x, b.y);
        }
        int col = nt * 8 + tig * 2;
        if (r0 < n)
            *(__half2*)(g_xwh + (size_t)r0 * D + col) = __floats2half2_rn(c[0], c[1]);
        if (r1 < n)
            *(__half2*)(g_xwh + (size_t)r1 * D + col) = __floats2half2_rn(c[2], c[3]);
    }
}

// ---------------- aggregation: warp/node, fp16 gathers, f32x2 FFMA2 --------
template <int FC>
__global__ void k_aggregate(const float* __restrict__ bias, int n,
                            const float* __restrict__ Wfc,
                            const float* __restrict__ bfc,
                            float* __restrict__ out) {
    int warp = (blockIdx.x * blockDim.x + threadIdx.x) >> 5;
    if (warp >= n) return;
    int lane = threadIdx.x & 31;
    int d = warp;
    float di = g_dinv[d];
    float self = di * di;

    uint2 us = *(const uint2*)(g_xwh + (size_t)d * D + lane * 4);
    float2 s0 = __half22float2(*(const __half2*)&us.x);
    float2 s1 = __half22float2(*(const __half2*)&us.y);
    unsigned long long acc01 = pk2(s0.x * self, s0.y * self);
    unsigned long long acc23 = pk2(s1.x * self, s1.y * self);

    int j0 = g_off[d], j1 = g_off[d + 1];
    for (int j = j0; j < j1; j++) {
        uint2 cp = g_csr[j];                 // warp-uniform, sequential
        float w  = __uint_as_float(cp.y);
        uint2 u = *(const uint2*)(g_xwh + (size_t)(int)cp.x * D + lane * 4);
        float2 f0 = __half22float2(*(const __half2*)&u.x);
        float2 f1 = __half22float2(*(const __half2*)&u.y);
        unsigned long long w2 = pk2(w, w);
        fma2(acc01, pk2(f0.x, f0.y), w2);    // 2 FMAs in one FFMA2
        fma2(acc23, pk2(f1.x, f1.y), w2);
    }
    float2 a01 = upk2(acc01);
    float2 a23 = upk2(acc23);
    float4 acc = make_float4(a01.x, a01.y, a23.x, a23.y);

    float4 b = *(const float4*)(bias + lane * 4);
    acc.x = fmaxf(acc.x + b.x, 0.f);
    acc.y = fmaxf(acc.y + b.y, 0.f);
    acc.z = fmaxf(acc.z + b.z, 0.f);
    acc.w = fmaxf(acc.w + b.w, 0.f);

    if (FC) {
        float4 wf = *(const float4*)(Wfc + lane * 4);
        float s = acc.x * wf.x + acc.y * wf.y + acc.z * wf.z + acc.w * wf.w;
#pragma unroll
        for (int o = 16; o; o >>= 1) s += __shfl_xor_sync(0xFFFFFFFFu, s, o);
        if (lane == 0) out[d] = s + bfc[0];
    } else {
        uint2 r;
        *(__half2*)&r.x = __floats2half2_rn(acc.x, acc.y);
        *(__half2*)&r.y = __floats2half2_rn(acc.z, acc.w);
        *(uint2*)(g_h + (size_t)d * D + lane * 4) = r;
    }
}

// ---------------- launch (graph fork/join: GEMM1 || CSR build) -------------
extern "C" void kernel_launch(void* const* d_in, const int* in_sizes, int n_in,
                              void* d_out, int out_size) {
    const float* x   = (const float*)d_in[0];
    const void*  ei  = d_in[1];
    const float* W1  = (const float*)d_in[2];
    const float* b1  = (const float*)d_in[3];
    const float* W2  = (const float*)d_in[4];
    const float* b2  = (const float*)d_in[5];
    const float* W3  = (const float*)d_in[6];
    const float* b3  = (const float*)d_in[7];
    const float* Wfc = (const float*)d_in[8];
    const float* bfc = (const float*)d_in[9];
    float* out = (float*)d_out;

    int n = in_sizes[0] / D;   // 50000
    int e = in_sizes[1] / 2;   // 800000

    int nb  = (n + 255) / 256;
    int eb  = (e + 255) / 256;
    int sb  = (n + 1023) / 1024;
    int gemm_grid = (n + 127) / 128;
    int warp_grid = (n + 7) / 8;

    // one-time setup on the first (non-captured) correctness call
    static cudaStream_t s2 = nullptr;
    static cudaEvent_t ev_fork = nullptr, ev_join = nullptr;
    if (!s2) {
        cudaStreamCreateWithFlags(&s2, cudaStreamNonBlocking);
        cudaEventCreateWithFlags(&ev_fork, cudaEventDisableTiming);
        cudaEventCreateWithFlags(&ev_join, cudaEventDisableTiming);
        cudaFuncSetAttribute(k_gemm_mma,
                             cudaFuncAttributeMaxDynamicSharedMemorySize, 32768);
    }

    k_init<<<48 + nb, 256>>>(W1, W2, W3, n);               // 0
    k_count<<<eb, 256>>>(ei, e);                           // 1

    // fork: GEMM1 (needs only x + W fragments) runs alongside the CSR build
    cudaEventRecord(ev_fork, 0);
    k_scan_p1<<<sb, 256>>>(n);                             // 2
    cudaStreamWaitEvent(s2, ev_fork, 0);
    k_gemm_mma<<<gemm_grid, 256, 32768, s2>>>(x, 0, n, 0); // 3 (parallel branch)
    cudaEventRecord(ev_join, s2);
    k_scan_p23<<<sb, 256>>>(n, sb);                        // 4
    k_fill<<<eb, 256>>>(ei, e);                            // 5
    cudaStreamWaitEvent(0, ev_join, 0);                    // join

    k_aggregate<0><<<warp_grid, 256>>>(b1, n, nullptr, nullptr, nullptr);  // 6
    k_gemm_mma<<<gemm_grid, 256, 32768>>>(x, 1, n, 1);                     // 7
    k_aggregate<0><<<warp_grid, 256>>>(b2, n, nullptr, nullptr, nullptr);  // 8
    k_gemm_mma<<<gemm_grid, 256, 32768>>>(x, 2, n, 1);                     // 9
    k_aggregate<1><<<warp_grid, 256>>>(b3, n, Wfc, bfc, out);              // 10
}